// round 1
// baseline (speedup 1.0000x reference)
#include <cuda_runtime.h>
#include <cstdint>
#include <math.h>

// ---------------- problem constants ----------------
#define BTC   192
#define NQC   64
#define NCC   1024
#define CCD   384
#define HCN   8
#define DHC   48
#define HIDC  1536
#define MROWS (BTC*NQC)     // 12288
#define CROWS (BTC*NCC)     // 196608

// ---------------- scratch (device globals; no allocs allowed) ----------------
__device__ float g_xn [MROWS*CCD];                 // LN(x) / LN(x1)
__device__ float g_cn [(size_t)CROWS*CCD];         // LN(context)
__device__ float g_q  [MROWS*CCD];                 // q
__device__ float g_kv [(size_t)CROWS*2*CCD];       // kv
__device__ float g_ob [MROWS*CCD];                 // attention output
__device__ float g_x1 [MROWS*CCD];                 // x + o@Wo + bo
__device__ float g_h  [MROWS*HIDC];                // gelu(xn2@W1+b1)
__device__ float g_mk [MROWS];                     // mask as float (1 keep / 0 uniform)

// ---------------- helpers ----------------
__device__ __forceinline__ float to_tf32(float x){
    uint32_t u; asm("cvt.rna.tf32.f32 %0, %1;" : "=r"(u) : "f"(x));
    return __uint_as_float(u);
}

__device__ __forceinline__ void mma8(float* c, float a0,float a1,float a2,float a3,
                                     float b0,float b1){
    asm volatile("mma.sync.aligned.m16n8k8.row.col.f32.tf32.tf32.f32 "
        "{%0,%1,%2,%3}, {%4,%5,%6,%7}, {%8,%9}, {%0,%1,%2,%3};\n"
        : "+f"(c[0]), "+f"(c[1]), "+f"(c[2]), "+f"(c[3])
        : "r"(__float_as_uint(a0)), "r"(__float_as_uint(a1)),
          "r"(__float_as_uint(a2)), "r"(__float_as_uint(a3)),
          "r"(__float_as_uint(b0)), "r"(__float_as_uint(b1)));
}

__device__ __forceinline__ float gelu_tanh(float x){
    float x3 = x*x*x;
    return 0.5f*x*(1.0f + tanhf(0.7978845608028654f*(x + 0.044715f*x3)));
}

// ---------------- LayerNorm: one warp per row of 384 ----------------
__global__ void __launch_bounds__(256) ln_kernel(const float* __restrict__ in,
        float* __restrict__ out, const float* __restrict__ g,
        const float* __restrict__ b, float eps){
    int warp = threadIdx.x >> 5, lane = threadIdx.x & 31;
    int row  = blockIdx.x * 8 + warp;
    const float4* ip = (const float4*)(in + (size_t)row*CCD);
    float4 v[3];
    float s = 0.f, ss = 0.f;
#pragma unroll
    for (int j=0;j<3;j++){
        v[j] = ip[lane + j*32];
        s  += v[j].x + v[j].y + v[j].z + v[j].w;
        ss += v[j].x*v[j].x + v[j].y*v[j].y + v[j].z*v[j].z + v[j].w*v[j].w;
    }
#pragma unroll
    for (int o=16;o;o>>=1){
        s  += __shfl_xor_sync(0xffffffffu, s,  o);
        ss += __shfl_xor_sync(0xffffffffu, ss, o);
    }
    float mean = s * (1.f/CCD);
    float var  = ss * (1.f/CCD) - mean*mean;
    float r    = rsqrtf(var + eps);
    float4* op = (float4*)(out + (size_t)row*CCD);
    if (g){
#pragma unroll
        for (int j=0;j<3;j++){
            float4 gg = ((const float4*)g)[lane + j*32];
            float4 bb = ((const float4*)b)[lane + j*32];
            float4 y;
            y.x = (v[j].x-mean)*r*gg.x + bb.x;
            y.y = (v[j].y-mean)*r*gg.y + bb.y;
            y.z = (v[j].z-mean)*r*gg.z + bb.z;
            y.w = (v[j].w-mean)*r*gg.w + bb.w;
            op[lane + j*32] = y;
        }
    } else {
#pragma unroll
        for (int j=0;j<3;j++){
            float4 y;
            y.x = (v[j].x-mean)*r; y.y = (v[j].y-mean)*r;
            y.z = (v[j].z-mean)*r; y.w = (v[j].w-mean)*r;
            op[lane + j*32] = y;
        }
    }
}

// ---------------- mask dtype classification + conversion ----------------
// bool  -> bytes at phase 1 are live mask values (~50% nonzero)
// float -> 1.0f has byte3 = 0x3f (phase 3 nonzero), phase 1 always 0
// int32 -> only phase 0 nonzero
__global__ void mask_conv(const unsigned char* __restrict__ m, float* __restrict__ out){
    __shared__ int cls1, cls3;
    if (threadIdx.x == 0){ cls1 = 0; cls3 = 0; }
    __syncthreads();
    int a1 = 0, a3 = 0;
    for (int i = threadIdx.x; i < MROWS; i += blockDim.x){
        if (m[i]){
            int ph = i & 3;
            if (ph == 1) a1 = 1;
            if (ph == 3) a3 = 1;
        }
    }
    if (a1) atomicOr(&cls1, 1);
    if (a3) atomicOr(&cls3, 1);
    __syncthreads();
    bool isb8  = (cls1 != 0);
    bool isf32 = (!isb8) && (cls3 != 0);
    for (int i = threadIdx.x; i < MROWS; i += blockDim.x){
        float v;
        if (isb8)       v = m[i] ? 1.f : 0.f;
        else if (isf32) v = (((const float*)m)[i] != 0.f) ? 1.f : 0.f;
        else            v = (((const int*)m)[i]   != 0  ) ? 1.f : 0.f;
        out[i] = v;
    }
}

// ---------------- tf32 GEMM: C = A(MxK) @ B(KxN) + bias, epilogues ----------------
// EPI 0: bias only.  EPI 1: bias + residual.  EPI 2: bias + gelu(tanh).
// All of M%128, N%64, K%16 are 0 for our shapes -> no edge guards.
template<int EPI>
__global__ void __launch_bounds__(256) gemm_tf32(const float* __restrict__ A,
        const float* __restrict__ B, const float* __restrict__ bias,
        const float* __restrict__ R, float* __restrict__ C_,
        int M, int N, int K){
    __shared__ float As[2][16][136];   // transposed A tile, pad 8 -> conflict-free
    __shared__ float Bs[2][16][72];
    const int tid = threadIdx.x, lane = tid & 31, wid = tid >> 5;
    const int l4 = lane & 3, ld4 = lane >> 2;
    const int m0 = blockIdx.y * 128, n0 = blockIdx.x * 64;
    const int wm = wid >> 1, wn = wid & 1;

    float acc[2][4][4];
#pragma unroll
    for (int mi=0;mi<2;mi++)
#pragma unroll
        for (int ni=0;ni<4;ni++)
#pragma unroll
            for (int j=0;j<4;j++) acc[mi][ni][j] = 0.f;

    const int ar0  = tid >> 2, aq  = tid & 3;   // rows ar0 and ar0+64
    const int brow = tid >> 4, bc4 = tid & 15;

    float4 pa0, pa1, pb;
    // prologue fetch tile 0
    {
        pa0 = *(const float4*)(A + (size_t)(m0+ar0   )*K + aq*4);
        pa1 = *(const float4*)(A + (size_t)(m0+ar0+64)*K + aq*4);
        pb  = *(const float4*)(B + (size_t)(brow)*N + n0 + bc4*4);
        As[0][aq*4+0][ar0] = to_tf32(pa0.x); As[0][aq*4+1][ar0] = to_tf32(pa0.y);
        As[0][aq*4+2][ar0] = to_tf32(pa0.z); As[0][aq*4+3][ar0] = to_tf32(pa0.w);
        As[0][aq*4+0][ar0+64] = to_tf32(pa1.x); As[0][aq*4+1][ar0+64] = to_tf32(pa1.y);
        As[0][aq*4+2][ar0+64] = to_tf32(pa1.z); As[0][aq*4+3][ar0+64] = to_tf32(pa1.w);
        Bs[0][brow][bc4*4+0] = to_tf32(pb.x); Bs[0][brow][bc4*4+1] = to_tf32(pb.y);
        Bs[0][brow][bc4*4+2] = to_tf32(pb.z); Bs[0][brow][bc4*4+3] = to_tf32(pb.w);
    }
    __syncthreads();

    const int nk = K >> 4;
    for (int kt = 0; kt < nk; kt++){
        const int buf = kt & 1;
        if (kt + 1 < nk){
            int k0 = (kt+1)*16;
            pa0 = *(const float4*)(A + (size_t)(m0+ar0   )*K + k0 + aq*4);
            pa1 = *(const float4*)(A + (size_t)(m0+ar0+64)*K + k0 + aq*4);
            pb  = *(const float4*)(B + (size_t)(k0+brow)*N + n0 + bc4*4);
        }
#pragma unroll
        for (int ks=0; ks<2; ks++){
            const int kk = ks*8;
            float af[2][4]; float bf[4][2];
#pragma unroll
            for (int mi=0;mi<2;mi++){
                int mr = wm*32 + mi*16 + ld4;
                af[mi][0] = As[buf][kk+l4  ][mr];
                af[mi][1] = As[buf][kk+l4  ][mr+8];
                af[mi][2] = As[buf][kk+l4+4][mr];
                af[mi][3] = As[buf][kk+l4+4][mr+8];
            }
#pragma unroll
            for (int ni=0;ni<4;ni++){
                int nn = wn*32 + ni*8 + ld4;
                bf[ni][0] = Bs[buf][kk+l4  ][nn];
                bf[ni][1] = Bs[buf][kk+l4+4][nn];
            }
#pragma unroll
            for (int mi=0;mi<2;mi++)
#pragma unroll
                for (int ni=0;ni<4;ni++)
                    mma8(acc[mi][ni], af[mi][0],af[mi][1],af[mi][2],af[mi][3],
                         bf[ni][0], bf[ni][1]);
        }
        if (kt + 1 < nk){
            const int nb = buf ^ 1;
            As[nb][aq*4+0][ar0] = to_tf32(pa0.x); As[nb][aq*4+1][ar0] = to_tf32(pa0.y);
            As[nb][aq*4+2][ar0] = to_tf32(pa0.z); As[nb][aq*4+3][ar0] = to_tf32(pa0.w);
            As[nb][aq*4+0][ar0+64] = to_tf32(pa1.x); As[nb][aq*4+1][ar0+64] = to_tf32(pa1.y);
            As[nb][aq*4+2][ar0+64] = to_tf32(pa1.z); As[nb][aq*4+3][ar0+64] = to_tf32(pa1.w);
            Bs[nb][brow][bc4*4+0] = to_tf32(pb.x); Bs[nb][brow][bc4*4+1] = to_tf32(pb.y);
            Bs[nb][brow][bc4*4+2] = to_tf32(pb.z); Bs[nb][brow][bc4*4+3] = to_tf32(pb.w);
        }
        __syncthreads();
    }

    // epilogue
#pragma unroll
    for (int mi=0;mi<2;mi++){
#pragma unroll
        for (int ni=0;ni<4;ni++){
            int row = m0 + wm*32 + mi*16 + ld4;
            int col = n0 + wn*32 + ni*8 + 2*l4;
            float b0v = bias[col], b1v = bias[col+1];
            float v0 = acc[mi][ni][0] + b0v, v1 = acc[mi][ni][1] + b1v;
            float v2 = acc[mi][ni][2] + b0v, v3 = acc[mi][ni][3] + b1v;
            if (EPI == 1){
                float2 r0 = *(const float2*)(R + (size_t)row*N + col);
                float2 r1 = *(const float2*)(R + (size_t)(row+8)*N + col);
                v0 += r0.x; v1 += r0.y; v2 += r1.x; v3 += r1.y;
            }
            if (EPI == 2){
                v0 = gelu_tanh(v0); v1 = gelu_tanh(v1);
                v2 = gelu_tanh(v2); v3 = gelu_tanh(v3);
            }
            float2 w0; w0.x = v0; w0.y = v1;
            float2 w1; w1.x = v2; w1.y = v3;
            *(float2*)(C_ + (size_t)row*N + col)     = w0;
            *(float2*)(C_ + (size_t)(row+8)*N + col) = w1;
        }
    }
}

// ---------------- fused attention: one block per (b,h), flash-style ----------------
// Q tile 64x48 (pre-scaled), KV chunks of 128, online softmax, tf32 mma for
// S = Q K^T and O += P V.  Masked rows: s forced to 0 -> P=1, l=1024 -> O = mean(V),
// exactly reproducing the fp32 -FLT_MAX-bias absorption in the reference.
#define ATTN_SMEM_FLOATS (64*52 + 128*52 + 128*56 + 64*132 + 4*64)

__global__ void __launch_bounds__(256) attn_kernel(const float* __restrict__ Q,
        const float* __restrict__ KV, const float* __restrict__ maskf,
        float* __restrict__ O){
    extern __shared__ float sm[];
    float (*Qs)[52]  = (float(*)[52]) (sm);
    float (*Ks)[52]  = (float(*)[52]) (sm + 64*52);
    float (*Vs)[56]  = (float(*)[56]) (sm + 64*52 + 128*52);
    float (*Ss)[132] = (float(*)[132])(sm + 64*52 + 128*52 + 128*56);
    float* m_s  = sm + 64*52 + 128*52 + 128*56 + 64*132;
    float* l_s  = m_s  + 64;
    float* sc_s = l_s  + 64;
    float* mk_s = sc_s + 64;

    const int b = blockIdx.y, h = blockIdx.x;
    const int tid = threadIdx.x, lane = tid & 31, wid = tid >> 5;
    const int l4 = lane & 3, ld4 = lane >> 2;
    const int wm = wid >> 1, wn = wid & 1;
    const int mr = wm*16 + ld4;
    const int srow = tid >> 2, sub = tid & 3;

    const float* qh = Q  + ((size_t)b*NQC)*CCD + h*DHC;
    const float* kh = KV + ((size_t)b*NCC)*(2*CCD) + h*DHC;
    const float* vh = kh + CCD;
    const float scale = 0.14433756729740643f;   // 48^-0.5

    for (int i = tid; i < 64*48; i += 256){
        int r = i/48, c = i - r*48;
        Qs[r][c] = to_tf32(qh[(size_t)r*CCD + c] * scale);
    }
    if (tid < 64){
        m_s[tid] = -1e30f; l_s[tid] = 0.f;
        mk_s[tid] = maskf[b*NQC + tid];
    }
    float oacc[3][4];
#pragma unroll
    for (int ni=0;ni<3;ni++)
#pragma unroll
        for (int j=0;j<4;j++) oacc[ni][j] = 0.f;
    __syncthreads();

    for (int c0 = 0; c0 < NCC; c0 += 128){
        // load K,V chunk (tf32-quantized)
        for (int i = tid; i < 128*48; i += 256){
            int r = i/48, c = i - r*48;
            Ks[r][c] = to_tf32(kh[(size_t)(c0+r)*(2*CCD) + c]);
            Vs[r][c] = to_tf32(vh[(size_t)(c0+r)*(2*CCD) + c]);
        }
        __syncthreads();

        // S = Q K^T : warp (wm,wn) -> rows [wm*16,+16), cols [wn*64,+64)
        float sacc[8][4];
#pragma unroll
        for (int ni=0;ni<8;ni++){ sacc[ni][0]=sacc[ni][1]=sacc[ni][2]=sacc[ni][3]=0.f; }
#pragma unroll
        for (int k=0;k<48;k+=8){
            float a0=Qs[mr][k+l4], a1=Qs[mr+8][k+l4];
            float a2=Qs[mr][k+l4+4], a3=Qs[mr+8][k+l4+4];
#pragma unroll
            for (int ni=0;ni<8;ni++){
                int nn = wn*64 + ni*8 + ld4;
                mma8(sacc[ni], a0,a1,a2,a3, Ks[nn][k+l4], Ks[nn][k+l4+4]);
            }
        }
#pragma unroll
        for (int ni=0;ni<8;ni++){
            int cc = wn*64 + ni*8 + 2*l4;
            Ss[mr  ][cc] = sacc[ni][0]; Ss[mr  ][cc+1] = sacc[ni][1];
            Ss[mr+8][cc] = sacc[ni][2]; Ss[mr+8][cc+1] = sacc[ni][3];
        }
        __syncthreads();

        // online softmax: 4 threads per row, 32 cols each
        {
            float keep = mk_s[srow];
            float mold = m_s[srow];
            float mx = -1e30f;
#pragma unroll 8
            for (int j=0;j<32;j++){
                float s = Ss[srow][sub*32 + j] * keep;
                mx = fmaxf(mx, s);
            }
            mx = fmaxf(mx, __shfl_xor_sync(0xffffffffu, mx, 1));
            mx = fmaxf(mx, __shfl_xor_sync(0xffffffffu, mx, 2));
            float mnew = fmaxf(mold, mx);
            float lsum = 0.f;
#pragma unroll 8
            for (int j=0;j<32;j++){
                int cc = sub*32 + j;
                float s = Ss[srow][cc] * keep;
                float p = __expf(s - mnew);
                lsum += p;
                Ss[srow][cc] = to_tf32(p);
            }
            lsum += __shfl_xor_sync(0xffffffffu, lsum, 1);
            lsum += __shfl_xor_sync(0xffffffffu, lsum, 2);
            if (sub == 0){
                float scl = __expf(mold - mnew);
                m_s[srow] = mnew;
                l_s[srow] = l_s[srow]*scl + lsum;
                sc_s[srow] = scl;
            }
        }
        __syncthreads();

        // rescale O, then O += P V  (warp: rows [wm*16,+16), cols [wn*24,+24))
        {
            float s0 = sc_s[mr], s1 = sc_s[mr+8];
#pragma unroll
            for (int ni=0;ni<3;ni++){
                oacc[ni][0]*=s0; oacc[ni][1]*=s0; oacc[ni][2]*=s1; oacc[ni][3]*=s1;
            }
#pragma unroll
            for (int k=0;k<128;k+=8){
                float a0=Ss[mr][k+l4], a1=Ss[mr+8][k+l4];
                float a2=Ss[mr][k+l4+4], a3=Ss[mr+8][k+l4+4];
#pragma unroll
                for (int ni=0;ni<3;ni++){
                    int nn = wn*24 + ni*8 + ld4;
                    mma8(oacc[ni], a0,a1,a2,a3, Vs[k+l4][nn], Vs[k+l4+4][nn]);
                }
            }
        }
        __syncthreads();
    }

    float inv0 = 1.f / l_s[mr];
    float inv1 = 1.f / l_s[mr+8];
#pragma unroll
    for (int ni=0;ni<3;ni++){
        int cc = wn*24 + ni*8 + 2*l4;
        size_t b0 = ((size_t)b*NQC + mr  )*CCD + h*DHC + cc;
        size_t b1 = ((size_t)b*NQC + mr+8)*CCD + h*DHC + cc;
        O[b0] = oacc[ni][0]*inv0; O[b0+1] = oacc[ni][1]*inv0;
        O[b1] = oacc[ni][2]*inv1; O[b1+1] = oacc[ni][3]*inv1;
    }
}

// ---------------- launcher ----------------
static float* sym_addr(const void* sym){
    void* p = nullptr;
    cudaGetSymbolAddress(&p, sym);
    return (float*)p;
}

extern "C" void kernel_launch(void* const* d_in, const int* in_sizes, int n_in,
                              void* d_out, int out_size){
    const float* x    = (const float*)d_in[0];
    const float* ctx  = (const float*)d_in[1];
    const unsigned char* mask = (const unsigned char*)d_in[2];
    const float* Wq   = (const float*)d_in[3];
    const float* bq   = (const float*)d_in[4];
    const float* Wkv  = (const float*)d_in[5];
    const float* bkv  = (const float*)d_in[6];
    const float* Wo   = (const float*)d_in[7];
    const float* bo   = (const float*)d_in[8];
    const float* gctx = (const float*)d_in[9];
    const float* bctx = (const float*)d_in[10];
    const float* W1   = (const float*)d_in[11];
    const float* b1   = (const float*)d_in[12];
    const float* W2   = (const float*)d_in[13];
    const float* b2   = (const float*)d_in[14];
    float* out = (float*)d_out;

    float* xn = sym_addr(g_xn);
    float* cn = sym_addr(g_cn);
    float* qb = sym_addr(g_q);
    float* kv = sym_addr(g_kv);
    float* ob = sym_addr(g_ob);
    float* x1 = sym_addr(g_x1);
    float* hb = sym_addr(g_h);
    float* mk = sym_addr(g_mk);

    const int smem_attn = ATTN_SMEM_FLOATS * 4;
    cudaFuncSetAttribute(attn_kernel, cudaFuncAttributeMaxDynamicSharedMemorySize, smem_attn);

    // 1. LN(x), LN(context), mask conversion
    ln_kernel<<<MROWS/8, 256>>>(x, xn, nullptr, nullptr, 1e-6f);
    ln_kernel<<<CROWS/8, 256>>>(ctx, cn, gctx, bctx, 1e-5f);
    mask_conv<<<1, 256>>>(mask, mk);

    // 2. q = xn@Wq + bq ; kv = cn@Wkv + bkv
    gemm_tf32<0><<<dim3(CCD/64,   MROWS/128), 256>>>(xn, Wq,  bq,  nullptr, qb, MROWS, CCD,   CCD);
    gemm_tf32<0><<<dim3(2*CCD/64, CROWS/128), 256>>>(cn, Wkv, bkv, nullptr, kv, CROWS, 2*CCD, CCD);

    // 3. attention
    attn_kernel<<<dim3(HCN, BTC), 256, smem_attn>>>(qb, kv, mk, ob);

    // 4. x1 = x + o@Wo + bo
    gemm_tf32<1><<<dim3(CCD/64, MROWS/128), 256>>>(ob, Wo, bo, x, x1, MROWS, CCD, CCD);

    // 5. MLP: out = x1 + gelu(LN(x1)@W1+b1)@W2 + b2
    ln_kernel<<<MROWS/8, 256>>>(x1, xn, nullptr, nullptr, 1e-6f);
    gemm_tf32<2><<<dim3(HIDC/64, MROWS/128), 256>>>(xn, W1, b1, nullptr, hb, MROWS, HIDC, CCD);
    gemm_tf32<1><<<dim3(CCD/64,  MROWS/128), 256>>>(hb, W2, b2, x1, out, MROWS, CCD, HIDC);
}

// round 2
// speedup vs baseline: 1.3681x; 1.3681x over previous
#include <cuda_runtime.h>
#include <cstdint>
#include <math.h>

// ---------------- problem constants ----------------
#define BTC   192
#define NQC   64
#define NCC   1024
#define CCD   384
#define HCN   8
#define DHC   48
#define HIDC  1536
#define MROWS (BTC*NQC)     // 12288
#define CROWS (BTC*NCC)     // 196608

// ---------------- scratch (device globals; no allocs allowed) ----------------
__device__ float g_xn [MROWS*CCD];                 // LN(x) / LN(x1)
__device__ float g_cn [(size_t)CROWS*CCD];         // LN(context)
__device__ float g_q  [MROWS*CCD];                 // q
__device__ float g_kv [(size_t)CROWS*2*CCD];       // kv
__device__ float g_ob [MROWS*CCD];                 // attention output
__device__ float g_x1 [MROWS*CCD];                 // x + o@Wo + bo
__device__ float g_h  [MROWS*HIDC];                // gelu(xn2@W1+b1)
__device__ float g_mk [MROWS];                     // mask as float (1 keep / 0 uniform)

// ---------------- helpers ----------------
__device__ __forceinline__ float to_tf32(float x){
    uint32_t u; asm("cvt.rna.tf32.f32 %0, %1;" : "=r"(u) : "f"(x));
    return __uint_as_float(u);
}

__device__ __forceinline__ void mma8(float* c, float a0,float a1,float a2,float a3,
                                     float b0,float b1){
    asm volatile("mma.sync.aligned.m16n8k8.row.col.f32.tf32.tf32.f32 "
        "{%0,%1,%2,%3}, {%4,%5,%6,%7}, {%8,%9}, {%0,%1,%2,%3};\n"
        : "+f"(c[0]), "+f"(c[1]), "+f"(c[2]), "+f"(c[3])
        : "r"(__float_as_uint(a0)), "r"(__float_as_uint(a1)),
          "r"(__float_as_uint(a2)), "r"(__float_as_uint(a3)),
          "r"(__float_as_uint(b0)), "r"(__float_as_uint(b1)));
}

__device__ __forceinline__ float gelu_tanh(float x){
    float x3 = x*x*x;
    return 0.5f*x*(1.0f + tanhf(0.7978845608028654f*(x + 0.044715f*x3)));
}

// ---------------- LayerNorm: one warp per row of 384 ----------------
__global__ void __launch_bounds__(256) ln_kernel(const float* __restrict__ in,
        float* __restrict__ out, const float* __restrict__ g,
        const float* __restrict__ b, float eps){
    int warp = threadIdx.x >> 5, lane = threadIdx.x & 31;
    int row  = blockIdx.x * 8 + warp;
    const float4* ip = (const float4*)(in + (size_t)row*CCD);
    float4 v[3];
    float s = 0.f, ss = 0.f;
#pragma unroll
    for (int j=0;j<3;j++){
        v[j] = ip[lane + j*32];
        s  += v[j].x + v[j].y + v[j].z + v[j].w;
        ss += v[j].x*v[j].x + v[j].y*v[j].y + v[j].z*v[j].z + v[j].w*v[j].w;
    }
#pragma unroll
    for (int o=16;o;o>>=1){
        s  += __shfl_xor_sync(0xffffffffu, s,  o);
        ss += __shfl_xor_sync(0xffffffffu, ss, o);
    }
    float mean = s * (1.f/CCD);
    float var  = ss * (1.f/CCD) - mean*mean;
    float r    = rsqrtf(var + eps);
    float4* op = (float4*)(out + (size_t)row*CCD);
    if (g){
#pragma unroll
        for (int j=0;j<3;j++){
            float4 gg = ((const float4*)g)[lane + j*32];
            float4 bb = ((const float4*)b)[lane + j*32];
            float4 y;
            y.x = (v[j].x-mean)*r*gg.x + bb.x;
            y.y = (v[j].y-mean)*r*gg.y + bb.y;
            y.z = (v[j].z-mean)*r*gg.z + bb.z;
            y.w = (v[j].w-mean)*r*gg.w + bb.w;
            op[lane + j*32] = y;
        }
    } else {
#pragma unroll
        for (int j=0;j<3;j++){
            float4 y;
            y.x = (v[j].x-mean)*r; y.y = (v[j].y-mean)*r;
            y.z = (v[j].z-mean)*r; y.w = (v[j].w-mean)*r;
            op[lane + j*32] = y;
        }
    }
}

// ---------------- mask dtype classification + conversion ----------------
__global__ void mask_conv(const unsigned char* __restrict__ m, float* __restrict__ out){
    __shared__ int cls1, cls3;
    if (threadIdx.x == 0){ cls1 = 0; cls3 = 0; }
    __syncthreads();
    int a1 = 0, a3 = 0;
    for (int i = threadIdx.x; i < MROWS; i += blockDim.x){
        if (m[i]){
            int ph = i & 3;
            if (ph == 1) a1 = 1;
            if (ph == 3) a3 = 1;
        }
    }
    if (a1) atomicOr(&cls1, 1);
    if (a3) atomicOr(&cls3, 1);
    __syncthreads();
    bool isb8  = (cls1 != 0);
    bool isf32 = (!isb8) && (cls3 != 0);
    for (int i = threadIdx.x; i < MROWS; i += blockDim.x){
        float v;
        if (isb8)       v = m[i] ? 1.f : 0.f;
        else if (isf32) v = (((const float*)m)[i] != 0.f) ? 1.f : 0.f;
        else            v = (((const int*)m)[i]   != 0  ) ? 1.f : 0.f;
        out[i] = v;
    }
}

// ---------------- tf32 GEMM v2: 128x128 CTA tile, 4 warps of 64x64 ----------------
// C = A(MxK) @ B(KxN) + bias; EPI 0: bias, 1: +residual, 2: gelu.
// A smem: transposed + xor-swizzled (col = m ^ ((k>>2)*8)) -> conflict-free
// both on store and on fragment load. B smem: [k][n] padded to 136.
// M%128==0, N%128==0, K%16==0 for all shapes used here.
template<int EPI>
__global__ void __launch_bounds__(128, 2) gemm_tf32(const float* __restrict__ A,
        const float* __restrict__ B, const float* __restrict__ bias,
        const float* __restrict__ R, float* __restrict__ C_,
        int M, int N, int K){
    __shared__ float As[2][16][136];
    __shared__ float Bs[2][16][136];
    const int tid = threadIdx.x, lane = tid & 31, wid = tid >> 5;
    const int l4 = lane & 3, ld4 = lane >> 2;
    const int m0 = blockIdx.y * 128, n0 = blockIdx.x * 128;
    const int wm = wid >> 1, wn = wid & 1;

    // staging thread mapping
    const int ar = tid >> 2, aq = tid & 3;        // A: rows ar+32g, k cols aq*4..+3
    const int br = tid >> 3, bc = tid & 7;        // B: row br, col chunks bc+8j

    float acc[4][8][4];
#pragma unroll
    for (int mt=0;mt<4;mt++)
#pragma unroll
        for (int ni=0;ni<8;ni++)
#pragma unroll
            for (int j=0;j<4;j++) acc[mt][ni][j] = 0.f;

    const float* Abase = A + (size_t)(m0 + ar)*K + aq*4;
    const float* Bbase = B + (size_t)br*N + n0 + bc*4;

    float4 pa[4], pb[4];
    // prologue: fetch k-tile 0
#pragma unroll
    for (int g=0;g<4;g++) pa[g] = *(const float4*)(Abase + (size_t)(32*g)*K);
#pragma unroll
    for (int j=0;j<4;j++) pb[j] = *(const float4*)(Bbase + (size_t)0*N + j*32);
    // store tile 0
    {
        const int xm = aq*8;
#pragma unroll
        for (int g=0;g<4;g++){
            int m = (ar + 32*g) ^ xm;
            As[0][aq*4+0][m] = to_tf32(pa[g].x);
            As[0][aq*4+1][m] = to_tf32(pa[g].y);
            As[0][aq*4+2][m] = to_tf32(pa[g].z);
            As[0][aq*4+3][m] = to_tf32(pa[g].w);
        }
#pragma unroll
        for (int j=0;j<4;j++){
            float4 w;
            w.x = to_tf32(pb[j].x); w.y = to_tf32(pb[j].y);
            w.z = to_tf32(pb[j].z); w.w = to_tf32(pb[j].w);
            *(float4*)&Bs[0][br][(bc + 8*j)*4] = w;
        }
    }
    __syncthreads();

    const int nk = K >> 4;
    for (int kt = 0; kt < nk; kt++){
        const int buf = kt & 1;
        if (kt + 1 < nk){
            const size_t k0 = (size_t)(kt+1)*16;
#pragma unroll
            for (int g=0;g<4;g++) pa[g] = *(const float4*)(Abase + (size_t)(32*g)*K + k0);
#pragma unroll
            for (int j=0;j<4;j++) pb[j] = *(const float4*)(Bbase + k0*N + j*32);
        }
#pragma unroll
        for (int ks=0; ks<2; ks++){
            const int kA  = ks*8 + l4;
            const int kA2 = kA + 4;
            const int xa  = (kA  >> 2) * 8;
            const int xa2 = (kA2 >> 2) * 8;
            float a[4][4]; float b[8][2];
#pragma unroll
            for (int mt=0;mt<4;mt++){
                int mc = wm*64 + mt*16 + ld4;
                a[mt][0] = As[buf][kA ][ mc      ^ xa ];
                a[mt][1] = As[buf][kA ][(mc + 8) ^ xa ];
                a[mt][2] = As[buf][kA2][ mc      ^ xa2];
                a[mt][3] = As[buf][kA2][(mc + 8) ^ xa2];
            }
#pragma unroll
            for (int ni=0;ni<8;ni++){
                int nn = wn*64 + ni*8 + ld4;
                b[ni][0] = Bs[buf][kA ][nn];
                b[ni][1] = Bs[buf][kA2][nn];
            }
#pragma unroll
            for (int mt=0;mt<4;mt++)
#pragma unroll
                for (int ni=0;ni<8;ni++)
                    mma8(acc[mt][ni], a[mt][0],a[mt][1],a[mt][2],a[mt][3],
                         b[ni][0], b[ni][1]);
        }
        if (kt + 1 < nk){
            const int nb = buf ^ 1;
            const int xm = aq*8;
#pragma unroll
            for (int g=0;g<4;g++){
                int m = (ar + 32*g) ^ xm;
                As[nb][aq*4+0][m] = to_tf32(pa[g].x);
                As[nb][aq*4+1][m] = to_tf32(pa[g].y);
                As[nb][aq*4+2][m] = to_tf32(pa[g].z);
                As[nb][aq*4+3][m] = to_tf32(pa[g].w);
            }
#pragma unroll
            for (int j=0;j<4;j++){
                float4 w;
                w.x = to_tf32(pb[j].x); w.y = to_tf32(pb[j].y);
                w.z = to_tf32(pb[j].z); w.w = to_tf32(pb[j].w);
                *(float4*)&Bs[nb][br][(bc + 8*j)*4] = w;
            }
        }
        __syncthreads();
    }

    // epilogue
#pragma unroll
    for (int mt=0;mt<4;mt++){
        int row = m0 + wm*64 + mt*16 + ld4;
#pragma unroll
        for (int ni=0;ni<8;ni++){
            int col = n0 + wn*64 + ni*8 + 2*l4;
            float b0v = bias[col], b1v = bias[col+1];
            float v0 = acc[mt][ni][0] + b0v, v1 = acc[mt][ni][1] + b1v;
            float v2 = acc[mt][ni][2] + b0v, v3 = acc[mt][ni][3] + b1v;
            if (EPI == 1){
                float2 r0 = *(const float2*)(R + (size_t)row*N + col);
                float2 r1 = *(const float2*)(R + (size_t)(row+8)*N + col);
                v0 += r0.x; v1 += r0.y; v2 += r1.x; v3 += r1.y;
            }
            if (EPI == 2){
                v0 = gelu_tanh(v0); v1 = gelu_tanh(v1);
                v2 = gelu_tanh(v2); v3 = gelu_tanh(v3);
            }
            float2 w0; w0.x = v0; w0.y = v1;
            float2 w1; w1.x = v2; w1.y = v3;
            *(float2*)(C_ + (size_t)row*N + col)     = w0;
            *(float2*)(C_ + (size_t)(row+8)*N + col) = w1;
        }
    }
}

// ---------------- fused attention (unchanged, known correct) ----------------
#define ATTN_SMEM_FLOATS (64*52 + 128*52 + 128*56 + 64*132 + 4*64)

__global__ void __launch_bounds__(256) attn_kernel(const float* __restrict__ Q,
        const float* __restrict__ KV, const float* __restrict__ maskf,
        float* __restrict__ O){
    extern __shared__ float sm[];
    float (*Qs)[52]  = (float(*)[52]) (sm);
    float (*Ks)[52]  = (float(*)[52]) (sm + 64*52);
    float (*Vs)[56]  = (float(*)[56]) (sm + 64*52 + 128*52);
    float (*Ss)[132] = (float(*)[132])(sm + 64*52 + 128*52 + 128*56);
    float* m_s  = sm + 64*52 + 128*52 + 128*56 + 64*132;
    float* l_s  = m_s  + 64;
    float* sc_s = l_s  + 64;
    float* mk_s = sc_s + 64;

    const int b = blockIdx.y, h = blockIdx.x;
    const int tid = threadIdx.x, lane = tid & 31, wid = tid >> 5;
    const int l4 = lane & 3, ld4 = lane >> 2;
    const int wm = wid >> 1, wn = wid & 1;
    const int mr = wm*16 + ld4;
    const int srow = tid >> 2, sub = tid & 3;

    const float* qh = Q  + ((size_t)b*NQC)*CCD + h*DHC;
    const float* kh = KV + ((size_t)b*NCC)*(2*CCD) + h*DHC;
    const float* vh = kh + CCD;
    const float scale = 0.14433756729740643f;   // 48^-0.5

    for (int i = tid; i < 64*48; i += 256){
        int r = i/48, c = i - r*48;
        Qs[r][c] = to_tf32(qh[(size_t)r*CCD + c] * scale);
    }
    if (tid < 64){
        m_s[tid] = -1e30f; l_s[tid] = 0.f;
        mk_s[tid] = maskf[b*NQC + tid];
    }
    float oacc[3][4];
#pragma unroll
    for (int ni=0;ni<3;ni++)
#pragma unroll
        for (int j=0;j<4;j++) oacc[ni][j] = 0.f;
    __syncthreads();

    for (int c0 = 0; c0 < NCC; c0 += 128){
        for (int i = tid; i < 128*48; i += 256){
            int r = i/48, c = i - r*48;
            Ks[r][c] = to_tf32(kh[(size_t)(c0+r)*(2*CCD) + c]);
            Vs[r][c] = to_tf32(vh[(size_t)(c0+r)*(2*CCD) + c]);
        }
        __syncthreads();

        float sacc[8][4];
#pragma unroll
        for (int ni=0;ni<8;ni++){ sacc[ni][0]=sacc[ni][1]=sacc[ni][2]=sacc[ni][3]=0.f; }
#pragma unroll
        for (int k=0;k<48;k+=8){
            float a0=Qs[mr][k+l4], a1=Qs[mr+8][k+l4];
            float a2=Qs[mr][k+l4+4], a3=Qs[mr+8][k+l4+4];
#pragma unroll
            for (int ni=0;ni<8;ni++){
                int nn = wn*64 + ni*8 + ld4;
                mma8(sacc[ni], a0,a1,a2,a3, Ks[nn][k+l4], Ks[nn][k+l4+4]);
            }
        }
#pragma unroll
        for (int ni=0;ni<8;ni++){
            int cc = wn*64 + ni*8 + 2*l4;
            Ss[mr  ][cc] = sacc[ni][0]; Ss[mr  ][cc+1] = sacc[ni][1];
            Ss[mr+8][cc] = sacc[ni][2]; Ss[mr+8][cc+1] = sacc[ni][3];
        }
        __syncthreads();

        {
            float keep = mk_s[srow];
            float mold = m_s[srow];
            float mx = -1e30f;
#pragma unroll 8
            for (int j=0;j<32;j++){
                float s = Ss[srow][sub*32 + j] * keep;
                mx = fmaxf(mx, s);
            }
            mx = fmaxf(mx, __shfl_xor_sync(0xffffffffu, mx, 1));
            mx = fmaxf(mx, __shfl_xor_sync(0xffffffffu, mx, 2));
            float mnew = fmaxf(mold, mx);
            float lsum = 0.f;
#pragma unroll 8
            for (int j=0;j<32;j++){
                int cc = sub*32 + j;
                float s = Ss[srow][cc] * keep;
                float p = __expf(s - mnew);
                lsum += p;
                Ss[srow][cc] = to_tf32(p);
            }
            lsum += __shfl_xor_sync(0xffffffffu, lsum, 1);
            lsum += __shfl_xor_sync(0xffffffffu, lsum, 2);
            if (sub == 0){
                float scl = __expf(mold - mnew);
                m_s[srow] = mnew;
                l_s[srow] = l_s[srow]*scl + lsum;
                sc_s[srow] = scl;
            }
        }
        __syncthreads();

        {
            float s0 = sc_s[mr], s1 = sc_s[mr+8];
#pragma unroll
            for (int ni=0;ni<3;ni++){
                oacc[ni][0]*=s0; oacc[ni][1]*=s0; oacc[ni][2]*=s1; oacc[ni][3]*=s1;
            }
#pragma unroll
            for (int k=0;k<128;k+=8){
                float a0=Ss[mr][k+l4], a1=Ss[mr+8][k+l4];
                float a2=Ss[mr][k+l4+4], a3=Ss[mr+8][k+l4+4];
#pragma unroll
                for (int ni=0;ni<3;ni++){
                    int nn = wn*24 + ni*8 + ld4;
                    mma8(oacc[ni], a0,a1,a2,a3, Vs[k+l4][nn], Vs[k+l4+4][nn]);
                }
            }
        }
        __syncthreads();
    }

    float inv0 = 1.f / l_s[mr];
    float inv1 = 1.f / l_s[mr+8];
#pragma unroll
    for (int ni=0;ni<3;ni++){
        int cc = wn*24 + ni*8 + 2*l4;
        size_t b0 = ((size_t)b*NQC + mr  )*CCD + h*DHC + cc;
        size_t b1 = ((size_t)b*NQC + mr+8)*CCD + h*DHC + cc;
        O[b0] = oacc[ni][0]*inv0; O[b0+1] = oacc[ni][1]*inv0;
        O[b1] = oacc[ni][2]*inv1; O[b1+1] = oacc[ni][3]*inv1;
    }
}

// ---------------- launcher ----------------
static float* sym_addr(const void* sym){
    void* p = nullptr;
    cudaGetSymbolAddress(&p, sym);
    return (float*)p;
}

extern "C" void kernel_launch(void* const* d_in, const int* in_sizes, int n_in,
                              void* d_out, int out_size){
    const float* x    = (const float*)d_in[0];
    const float* ctx  = (const float*)d_in[1];
    const unsigned char* mask = (const unsigned char*)d_in[2];
    const float* Wq   = (const float*)d_in[3];
    const float* bq   = (const float*)d_in[4];
    const float* Wkv  = (const float*)d_in[5];
    const float* bkv  = (const float*)d_in[6];
    const float* Wo   = (const float*)d_in[7];
    const float* bo   = (const float*)d_in[8];
    const float* gctx = (const float*)d_in[9];
    const float* bctx = (const float*)d_in[10];
    const float* W1   = (const float*)d_in[11];
    const float* b1   = (const float*)d_in[12];
    const float* W2   = (const float*)d_in[13];
    const float* b2   = (const float*)d_in[14];
    float* out = (float*)d_out;

    float* xn = sym_addr(g_xn);
    float* cn = sym_addr(g_cn);
    float* qb = sym_addr(g_q);
    float* kv = sym_addr(g_kv);
    float* ob = sym_addr(g_ob);
    float* x1 = sym_addr(g_x1);
    float* hb = sym_addr(g_h);
    float* mk = sym_addr(g_mk);

    const int smem_attn = ATTN_SMEM_FLOATS * 4;
    cudaFuncSetAttribute(attn_kernel, cudaFuncAttributeMaxDynamicSharedMemorySize, smem_attn);

    // 1. LN(x), LN(context), mask conversion
    ln_kernel<<<MROWS/8, 256>>>(x, xn, nullptr, nullptr, 1e-6f);
    ln_kernel<<<CROWS/8, 256>>>(ctx, cn, gctx, bctx, 1e-5f);
    mask_conv<<<1, 256>>>(mask, mk);

    // 2. q = xn@Wq + bq ; kv = cn@Wkv + bkv
    gemm_tf32<0><<<dim3(CCD/128,   MROWS/128), 128>>>(xn, Wq,  bq,  nullptr, qb, MROWS, CCD,   CCD);
    gemm_tf32<0><<<dim3(2*CCD/128, CROWS/128), 128>>>(cn, Wkv, bkv, nullptr, kv, CROWS, 2*CCD, CCD);

    // 3. attention
    attn_kernel<<<dim3(HCN, BTC), 256, smem_attn>>>(qb, kv, mk, ob);

    // 4. x1 = x + o@Wo + bo
    gemm_tf32<1><<<dim3(CCD/128, MROWS/128), 128>>>(ob, Wo, bo, x, x1, MROWS, CCD, CCD);

    // 5. MLP: out = x1 + gelu(LN(x1)@W1+b1)@W2 + b2
    ln_kernel<<<MROWS/8, 256>>>(x1, xn, nullptr, nullptr, 1e-6f);
    gemm_tf32<2><<<dim3(HIDC/128, MROWS/128), 128>>>(xn, W1, b1, nullptr, hb, MROWS, HIDC, CCD);
    gemm_tf32<1><<<dim3(CCD/128,  MROWS/128), 128>>>(hb, W2, b2, x1, out, MROWS, CCD, HIDC);
}